// round 2
// baseline (speedup 1.0000x reference)
#include <cuda_runtime.h>

// Problem constants (fixed by the reference)
#define BATCH   2048
#define NF      32
#define NP      496
#define NU      (NF + NP)   // 528 total units (32 mains + 496 pairs)
#define EMB     32
#define HID     64
#define MROWS   64          // batch rows per CTA
#define NTHREADS 64
#define AST     64          // sAT row stride (floats)

// Deterministic partial-output scratch: partial[unit][b]
__device__ float g_partial[NU * BATCH];

__device__ __forceinline__ float gate_of(float z) {
    // smooth_z with gamma = 1
    if (z <= -0.5f) return 0.0f;
    if (z >=  0.5f) return 1.0f;
    return (-2.0f * z * z + 1.5f) * z + 0.5f;   // -2 z^3 + 1.5 z + 0.5
}

// One CTA: unit u (feature or pair MLP), 64 batch rows.
// Layer sizes: [64 x K1] @ [K1 x 64] -> relu -> [64 x 64] @ [64 x 64] -> relu -> dot w2.
// 64 threads, each computes an 8x8 tile of each GEMM.
template<int K1, bool PAIR>
__global__ void __launch_bounds__(NTHREADS)
mlp_kernel(const int*   __restrict__ idx_main,    // mains  [B, NF]
           const int*   __restrict__ idx_pairs,   // pairs  [B, NP, 2]
           const int*   __restrict__ pairs_list,  // [NP, 2]
           const int*   __restrict__ offsets,     // [NF]
           const float* __restrict__ emb,         // [2048, 32]
           const float* __restrict__ w0,          // [U, K1, 64]
           const float* __restrict__ w1,          // [U, 64, 64]
           const float* __restrict__ w2,          // [U, 64]
           const float* __restrict__ b0,          // [U, 64]
           const float* __restrict__ b1,          // [U, 64]
           const float* __restrict__ b2,          // [U]
           const float* __restrict__ z,           // [U]
           int unit_base)
{
    extern __shared__ float smem[];
    float* sW0  = smem;                    // K1*64
    float* sW1  = sW0 + K1 * 64;           // 64*64
    float* sAT  = sW1 + 64 * 64;           // 64 x AST (A^T, later H0^T)
    float* sB0  = sAT + 64 * AST;          // 64
    float* sB1  = sB0 + 64;                // 64
    float* sW2  = sB1 + 64;                // 64
    float* sMisc = sW2 + 64;               // [0]=gate, [1]=b2

    const int u      = blockIdx.x;
    const int m_base = blockIdx.y * MROWS;
    const int tid    = threadIdx.x;

    // ---- stage weights / biases into smem ----
    {
        const float4* s0 = (const float4*)(w0 + (size_t)u * (K1 * 64));
        float4* d0 = (float4*)sW0;
        #pragma unroll
        for (int i = tid; i < K1 * 16; i += NTHREADS) d0[i] = s0[i];

        const float4* s1 = (const float4*)(w1 + (size_t)u * 4096);
        float4* d1 = (float4*)sW1;
        #pragma unroll
        for (int i = tid; i < 1024; i += NTHREADS) d1[i] = s1[i];

        sB0[tid] = b0[u * 64 + tid];
        sB1[tid] = b1[u * 64 + tid];
        sW2[tid] = w2[u * 64 + tid];
        if (tid == 0) { sMisc[0] = gate_of(z[u]); sMisc[1] = b2[u]; }
    }

    // ---- gather input activations A^T (row m = tid handles one batch row) ----
    {
        const int b = m_base + tid;
        if (PAIR) {
            const int f0 = pairs_list[u * 2 + 0];
            const int f1 = pairs_list[u * 2 + 1];
            const int i0 = idx_pairs[(size_t)b * (NP * 2) + u * 2 + 0] + offsets[f0];
            const int i1 = idx_pairs[(size_t)b * (NP * 2) + u * 2 + 1] + offsets[f1];
            const float4* e0 = (const float4*)(emb + (size_t)i0 * EMB);
            const float4* e1 = (const float4*)(emb + (size_t)i1 * EMB);
            #pragma unroll
            for (int kk = 0; kk < 8; kk++) {
                float4 v = e0[kk];
                sAT[(kk * 4 + 0) * AST + tid] = v.x;
                sAT[(kk * 4 + 1) * AST + tid] = v.y;
                sAT[(kk * 4 + 2) * AST + tid] = v.z;
                sAT[(kk * 4 + 3) * AST + tid] = v.w;
            }
            #pragma unroll
            for (int kk = 0; kk < 8; kk++) {
                float4 v = e1[kk];
                sAT[(32 + kk * 4 + 0) * AST + tid] = v.x;
                sAT[(32 + kk * 4 + 1) * AST + tid] = v.y;
                sAT[(32 + kk * 4 + 2) * AST + tid] = v.z;
                sAT[(32 + kk * 4 + 3) * AST + tid] = v.w;
            }
        } else {
            const int i0 = idx_main[(size_t)b * NF + u] + offsets[u];
            const float4* e0 = (const float4*)(emb + (size_t)i0 * EMB);
            #pragma unroll
            for (int kk = 0; kk < 8; kk++) {
                float4 v = e0[kk];
                sAT[(kk * 4 + 0) * AST + tid] = v.x;
                sAT[(kk * 4 + 1) * AST + tid] = v.y;
                sAT[(kk * 4 + 2) * AST + tid] = v.z;
                sAT[(kk * 4 + 3) * AST + tid] = v.w;
            }
        }
    }
    __syncthreads();

    const int tm = tid >> 3;
    const int tn = tid & 7;
    const int m0 = tm * 8;
    const int n0 = tn * 8;

    float acc[8][8];

    // ---- GEMM1: H0 = relu(A @ W0 + b0) ----
    #pragma unroll
    for (int i = 0; i < 8; i++)
        #pragma unroll
        for (int j = 0; j < 8; j++) acc[i][j] = 0.0f;

    #pragma unroll 8
    for (int k = 0; k < K1; k++) {
        float4 a0  = *(const float4*)&sAT[k * AST + m0];
        float4 a1  = *(const float4*)&sAT[k * AST + m0 + 4];
        float4 wv0 = *(const float4*)&sW0[k * 64 + n0];
        float4 wv1 = *(const float4*)&sW0[k * 64 + n0 + 4];
        float a[8] = {a0.x, a0.y, a0.z, a0.w, a1.x, a1.y, a1.z, a1.w};
        float w[8] = {wv0.x, wv0.y, wv0.z, wv0.w, wv1.x, wv1.y, wv1.z, wv1.w};
        #pragma unroll
        for (int i = 0; i < 8; i++)
            #pragma unroll
            for (int j = 0; j < 8; j++)
                acc[i][j] += a[i] * w[j];
    }
    __syncthreads();   // everyone done reading sAT

    // write H0^T over sAT (rows indexed by hidden-unit n)
    #pragma unroll
    for (int j = 0; j < 8; j++) {
        const float bj = sB0[n0 + j];
        #pragma unroll
        for (int i = 0; i < 8; i++) {
            float h = acc[i][j] + bj;
            sAT[(n0 + j) * AST + m0 + i] = h > 0.0f ? h : 0.0f;
        }
    }
    __syncthreads();

    // ---- GEMM2: H1 = relu(H0 @ W1 + b1), fused with dot(w2) epilogue ----
    #pragma unroll
    for (int i = 0; i < 8; i++)
        #pragma unroll
        for (int j = 0; j < 8; j++) acc[i][j] = 0.0f;

    #pragma unroll 8
    for (int k = 0; k < 64; k++) {
        float4 a0  = *(const float4*)&sAT[k * AST + m0];
        float4 a1  = *(const float4*)&sAT[k * AST + m0 + 4];
        float4 wv0 = *(const float4*)&sW1[k * 64 + n0];
        float4 wv1 = *(const float4*)&sW1[k * 64 + n0 + 4];
        float a[8] = {a0.x, a0.y, a0.z, a0.w, a1.x, a1.y, a1.z, a1.w};
        float w[8] = {wv0.x, wv0.y, wv0.z, wv0.w, wv1.x, wv1.y, wv1.z, wv1.w};
        #pragma unroll
        for (int i = 0; i < 8; i++)
            #pragma unroll
            for (int j = 0; j < 8; j++)
                acc[i][j] += a[i] * w[j];
    }

    // per-thread partial of o[m] = sum_n relu(h1)*w2[n]
    float po[8];
    #pragma unroll
    for (int i = 0; i < 8; i++) po[i] = 0.0f;
    #pragma unroll
    for (int j = 0; j < 8; j++) {
        const float bj = sB1[n0 + j];
        const float wj = sW2[n0 + j];
        #pragma unroll
        for (int i = 0; i < 8; i++) {
            float h = acc[i][j] + bj;
            h = h > 0.0f ? h : 0.0f;
            po[i] += h * wj;
        }
    }

    // reduce over the 8 threads sharing the same row block (lanes tn=0..7)
    #pragma unroll
    for (int off = 4; off > 0; off >>= 1)
        #pragma unroll
        for (int i = 0; i < 8; i++)
            po[i] += __shfl_down_sync(0xffffffffu, po[i], off, 8);

    if (tn == 0) {
        const float g  = sMisc[0];
        const float bb = sMisc[1];
        float* dst = g_partial + (size_t)(unit_base + u) * BATCH + m_base + m0;
        #pragma unroll
        for (int i = 0; i < 8; i++)
            dst[i] = g * (po[i] + bb);
    }
}

// Deterministic column-sum of the 528 unit partials.
__global__ void reduce_kernel(float* __restrict__ out)
{
    const int b = blockIdx.x * blockDim.x + threadIdx.x;
    float s0 = 0.f, s1 = 0.f, s2 = 0.f, s3 = 0.f;
    #pragma unroll 4
    for (int u = 0; u < NU; u += 4) {          // 528 % 4 == 0
        s0 += g_partial[(size_t)(u + 0) * BATCH + b];
        s1 += g_partial[(size_t)(u + 1) * BATCH + b];
        s2 += g_partial[(size_t)(u + 2) * BATCH + b];
        s3 += g_partial[(size_t)(u + 3) * BATCH + b];
    }
    out[b] = (s0 + s1) + (s2 + s3);
}

extern "C" void kernel_launch(void* const* d_in, const int* in_sizes, int n_in,
                              void* d_out, int out_size)
{
    (void)in_sizes; (void)n_in; (void)out_size;

    const int*   mains      = (const int*)d_in[0];
    const int*   pairs      = (const int*)d_in[1];
    const int*   pairs_list = (const int*)d_in[2];
    const int*   offsets    = (const int*)d_in[3];
    const float* emb        = (const float*)d_in[4];
    const float* mw0 = (const float*)d_in[5];
    const float* mw1 = (const float*)d_in[6];
    const float* mw2 = (const float*)d_in[7];
    const float* mb0 = (const float*)d_in[8];
    const float* mb1 = (const float*)d_in[9];
    const float* mb2 = (const float*)d_in[10];
    const float* pw0 = (const float*)d_in[11];
    const float* pw1 = (const float*)d_in[12];
    const float* pw2 = (const float*)d_in[13];
    const float* pb0 = (const float*)d_in[14];
    const float* pb1 = (const float*)d_in[15];
    const float* pb2 = (const float*)d_in[16];
    const float* z_main  = (const float*)d_in[17];
    const float* z_pairs = (const float*)d_in[18];
    float* out = (float*)d_out;

    const int smem_main = (32 * 64 + 4096 + 64 * AST + 3 * 64 + 4) * (int)sizeof(float);
    const int smem_pair = (64 * 64 + 4096 + 64 * AST + 3 * 64 + 4) * (int)sizeof(float);

    cudaFuncSetAttribute(mlp_kernel<32, false>,
                         cudaFuncAttributeMaxDynamicSharedMemorySize, smem_main);
    cudaFuncSetAttribute(mlp_kernel<64, true>,
                         cudaFuncAttributeMaxDynamicSharedMemorySize, smem_pair);

    // main effects: 32 units x 32 batch chunks
    mlp_kernel<32, false><<<dim3(NF, BATCH / MROWS), NTHREADS, smem_main>>>(
        mains, pairs, pairs_list, offsets, emb,
        mw0, mw1, mw2, mb0, mb1, mb2, z_main, 0);

    // pair effects: 496 units x 32 batch chunks
    mlp_kernel<64, true><<<dim3(NP, BATCH / MROWS), NTHREADS, smem_pair>>>(
        mains, pairs, pairs_list, offsets, emb,
        pw0, pw1, pw2, pb0, pb1, pb2, z_pairs, NF);

    // deterministic final sum
    reduce_kernel<<<BATCH / 256, 256>>>(out);
}

// round 4
// speedup vs baseline: 4.3029x; 4.3029x over previous
#include <cuda_runtime.h>
#include <cuda_fp16.h>
#include <cstdint>

#define BATCH   2048
#define NF      32
#define NP      496
#define NU      528
#define EMB     32
#define MROWS   128
#define NTHREADS 128

// fp16 preconverted tensors
__device__ __half g_W0[(size_t)NU * 4096];   // [u][n][k]  (transposed, mains k>=32 zeroed)
__device__ __half g_W1[(size_t)NU * 4096];   // [u][n][k]
__device__ __half g_emb[2048 * EMB];
__device__ float  g_w2[(size_t)NU * 64];
__device__ float  g_partial[(size_t)NU * BATCH];

__device__ __forceinline__ float gate_of(float z) {
    if (z <= -0.5f) return 0.0f;
    if (z >=  0.5f) return 1.0f;
    return (-2.0f * z * z + 1.5f) * z + 0.5f;
}

// ---------------- preconversion ----------------
__global__ void conv_weights(const float* __restrict__ mw0, const float* __restrict__ mw1,
                             const float* __restrict__ pw0, const float* __restrict__ pw1)
{
    __shared__ __half sh[64 * 65];
    const int u = blockIdx.x;
    const int t = threadIdx.x;

    if (u < NF) {
        const float* src = mw0 + (size_t)u * (32 * 64);
        for (int i = t; i < 4096; i += 256) {
            int k = i >> 6, n = i & 63;
            sh[k * 65 + n] = __float2half_rn(k < 32 ? src[k * 64 + n] : 0.0f);
        }
    } else {
        const float* src = pw0 + (size_t)(u - NF) * 4096;
        for (int i = t; i < 4096; i += 256) {
            int k = i >> 6, n = i & 63;
            sh[k * 65 + n] = __float2half_rn(src[i]);
        }
    }
    __syncthreads();
    for (int i = t; i < 4096; i += 256) {          // i = n*64 + k
        int n = i >> 6, k = i & 63;
        g_W0[(size_t)u * 4096 + i] = sh[k * 65 + n];
    }
    __syncthreads();
    {
        const float* src = (u < NF) ? mw1 + (size_t)u * 4096 : pw1 + (size_t)(u - NF) * 4096;
        for (int i = t; i < 4096; i += 256) {
            int k = i >> 6, n = i & 63;
            sh[k * 65 + n] = __float2half_rn(src[i]);
        }
    }
    __syncthreads();
    for (int i = t; i < 4096; i += 256) {
        int n = i >> 6, k = i & 63;
        g_W1[(size_t)u * 4096 + i] = sh[k * 65 + n];
    }
}

__global__ void conv_emb(const float* __restrict__ emb)
{
    int i = blockIdx.x * blockDim.x + threadIdx.x;
    if (i < 2048 * EMB) g_emb[i] = __float2half_rn(emb[i]);
}

__global__ void conv_w2(const float* __restrict__ mw2, const float* __restrict__ pw2)
{
    int i = blockIdx.x * blockDim.x + threadIdx.x;
    if (i < NU * 64) {
        int u = i >> 6, n = i & 63;
        g_w2[i] = (u < NF) ? mw2[u * 64 + n] : pw2[(size_t)(u - NF) * 64 + n];
    }
}

// ---------------- mma helpers ----------------
__device__ __forceinline__ void ldm_x4(uint32_t& r0, uint32_t& r1, uint32_t& r2, uint32_t& r3,
                                       uint32_t addr) {
    asm volatile("ldmatrix.sync.aligned.m8n8.x4.shared.b16 {%0,%1,%2,%3}, [%4];"
                 : "=r"(r0), "=r"(r1), "=r"(r2), "=r"(r3) : "r"(addr));
}
__device__ __forceinline__ void ldm_x2(uint32_t& r0, uint32_t& r1, uint32_t addr) {
    asm volatile("ldmatrix.sync.aligned.m8n8.x2.shared.b16 {%0,%1}, [%2];"
                 : "=r"(r0), "=r"(r1) : "r"(addr));
}
__device__ __forceinline__ void mma16816(float* c, const uint32_t* a, const uint32_t* b) {
    asm volatile(
        "mma.sync.aligned.m16n8k16.row.col.f32.f16.f16.f32 "
        "{%0,%1,%2,%3}, {%4,%5,%6,%7}, {%8,%9}, {%0,%1,%2,%3};"
        : "+f"(c[0]), "+f"(c[1]), "+f"(c[2]), "+f"(c[3])
        : "r"(a[0]), "r"(a[1]), "r"(a[2]), "r"(a[3]), "r"(b[0]), "r"(b[1]));
}

__device__ __forceinline__ uint32_t swz(uint32_t off) {      // SW128 xor swizzle, 128B rows
    return off ^ ((off >> 3) & 0x70);
}

// ---------------- main kernel ----------------
__global__ void __launch_bounds__(NTHREADS)
mlp_mma(const int*   __restrict__ mains,
        const int*   __restrict__ pairs,
        const int*   __restrict__ pairs_list,
        const int*   __restrict__ offsets,
        const float* __restrict__ mb0, const float* __restrict__ mb1,
        const float* __restrict__ mb2,
        const float* __restrict__ pb0, const float* __restrict__ pb1,
        const float* __restrict__ pb2,
        const float* __restrict__ z_main, const float* __restrict__ z_pairs)
{
    __shared__ __half sA[MROWS * 64];     // 16KB, 128B rows, swizzled
    __shared__ __half sW0[64 * 64];       // 8KB,  [n][k] rows, swizzled
    __shared__ __half sW1[64 * 64];       // 8KB
    __shared__ float  sb0[64], sb1[64], sw2[64];
    __shared__ float  sgate, sbias2;

    const int u      = blockIdx.x;
    const int m_base = blockIdx.y * MROWS;
    const int tid    = threadIdx.x;
    const int warp   = tid >> 5;
    const int lane   = tid & 31;

    const uint32_t aBase  = (uint32_t)__cvta_generic_to_shared(sA);
    const uint32_t w0Base = (uint32_t)__cvta_generic_to_shared(sW0);
    const uint32_t w1Base = (uint32_t)__cvta_generic_to_shared(sW1);

    // ---- stage weights (swizzled) ----
    {
        const uint4* s0 = (const uint4*)(g_W0 + (size_t)u * 4096);
        const uint4* s1 = (const uint4*)(g_W1 + (size_t)u * 4096);
        #pragma unroll
        for (int i = tid; i < 512; i += NTHREADS) {          // i = n*8 + chunk
            uint32_t off = (uint32_t)(i << 4);
            uint32_t sw = swz(off);
            *(uint4*)((char*)sW0 + sw) = s0[i];
            *(uint4*)((char*)sW1 + sw) = s1[i];
        }
    }
    // ---- biases / w2 / gate ----
    {
        const float* b0p = (u < NF) ? mb0 + (size_t)u * 64 : pb0 + (size_t)(u - NF) * 64;
        const float* b1p = (u < NF) ? mb1 + (size_t)u * 64 : pb1 + (size_t)(u - NF) * 64;
        if (tid < 64) {
            sb0[tid] = b0p[tid];
            sb1[tid] = b1p[tid];
            sw2[tid] = g_w2[(size_t)u * 64 + tid];
        }
        if (tid == 64) {
            sgate  = (u < NF) ? gate_of(z_main[u]) : gate_of(z_pairs[u - NF]);
        }
        if (tid == 65) {
            sbias2 = (u < NF) ? mb2[u] : pb2[u - NF];
        }
    }

    // ---- gather activations: one thread = one batch row (128B swizzled row) ----
    {
        const int b   = m_base + tid;
        const int row = tid;
        if (u >= NF) {
            const int up = u - NF;
            const int f0 = pairs_list[up * 2 + 0];
            const int f1 = pairs_list[up * 2 + 1];
            const int i0 = pairs[(size_t)b * (NP * 2) + up * 2 + 0] + offsets[f0];
            const int i1 = pairs[(size_t)b * (NP * 2) + up * 2 + 1] + offsets[f1];
            const uint4* e0 = (const uint4*)(g_emb + (size_t)i0 * EMB);
            const uint4* e1 = (const uint4*)(g_emb + (size_t)i1 * EMB);
            #pragma unroll
            for (int q = 0; q < 4; q++) {
                uint32_t off = (uint32_t)(row * 128 + q * 16);
                *(uint4*)((char*)sA + swz(off)) = e0[q];
            }
            #pragma unroll
            for (int q = 0; q < 4; q++) {
                uint32_t off = (uint32_t)(row * 128 + (4 + q) * 16);
                *(uint4*)((char*)sA + swz(off)) = e1[q];
            }
        } else {
            const int i0 = mains[(size_t)b * NF + u] + offsets[u];
            const uint4* e0 = (const uint4*)(g_emb + (size_t)i0 * EMB);
            const uint4 zero = {0u, 0u, 0u, 0u};
            #pragma unroll
            for (int q = 0; q < 4; q++) {
                uint32_t off = (uint32_t)(row * 128 + q * 16);
                *(uint4*)((char*)sA + swz(off)) = e0[q];
            }
            #pragma unroll
            for (int q = 0; q < 4; q++) {
                uint32_t off = (uint32_t)(row * 128 + (4 + q) * 16);
                *(uint4*)((char*)sA + swz(off)) = zero;
            }
        }
    }
    __syncthreads();

    const int mrow0 = warp * 32;          // this warp's 32 rows
    const int matA  = lane >> 3;          // 0..3
    const int rA    = lane & 7;
    const int matB  = (lane >> 3) & 1;    // x2 uses lanes 0-15; others harmless

    float acc[2][8][4];

    // ================= layer 0 =================
    #pragma unroll
    for (int mt = 0; mt < 2; mt++)
        #pragma unroll
        for (int nt = 0; nt < 8; nt++)
            #pragma unroll
            for (int c = 0; c < 4; c++) acc[mt][nt][c] = 0.0f;

    #pragma unroll
    for (int ks = 0; ks < 4; ks++) {
        uint32_t af[2][4];
        #pragma unroll
        for (int mt = 0; mt < 2; mt++) {
            int arow = mrow0 + mt * 16 + (matA & 1) * 8 + rA;
            uint32_t off = (uint32_t)(arow * 128 + ks * 32 + (matA >> 1) * 16);
            ldm_x4(af[mt][0], af[mt][1], af[mt][2], af[mt][3], aBase + swz(off));
        }
        #pragma unroll
        for (int nt = 0; nt < 8; nt++) {
            uint32_t bf[2];
            int brow = nt * 8 + rA;
            uint32_t boff = (uint32_t)(brow * 128 + ks * 32 + matB * 16);
            ldm_x2(bf[0], bf[1], w0Base + swz(boff));
            mma16816(acc[0][nt], af[0], bf);
            mma16816(acc[1][nt], af[1], bf);
        }
    }
    __syncthreads();    // all warps done reading sA

    // ---- epilogue 0: bias+relu -> half2 back into sA ----
    #pragma unroll
    for (int mt = 0; mt < 2; mt++) {
        #pragma unroll
        for (int nt = 0; nt < 8; nt++) {
            int n  = nt * 8 + (lane & 3) * 2;
            int r0 = mrow0 + mt * 16 + (lane >> 2);
            float lo = fmaxf(acc[mt][nt][0] + sb0[n],     0.0f);
            float hi = fmaxf(acc[mt][nt][1] + sb0[n + 1], 0.0f);
            __half2 h01 = __floats2half2_rn(lo, hi);
            uint32_t off0 = (uint32_t)(r0 * 128 + n * 2);
            *(uint32_t*)((char*)sA + swz(off0)) = *(uint32_t*)&h01;

            int r1 = r0 + 8;
            float lo2 = fmaxf(acc[mt][nt][2] + sb0[n],     0.0f);
            float hi2 = fmaxf(acc[mt][nt][3] + sb0[n + 1], 0.0f);
            __half2 h23 = __floats2half2_rn(lo2, hi2);
            uint32_t off1 = (uint32_t)(r1 * 128 + n * 2);
            *(uint32_t*)((char*)sA + swz(off1)) = *(uint32_t*)&h23;
        }
    }
    __syncthreads();

    // ================= layer 1 =================
    #pragma unroll
    for (int mt = 0; mt < 2; mt++)
        #pragma unroll
        for (int nt = 0; nt < 8; nt++)
            #pragma unroll
            for (int c = 0; c < 4; c++) acc[mt][nt][c] = 0.0f;

    #pragma unroll
    for (int ks = 0; ks < 4; ks++) {
        uint32_t af[2][4];
        #pragma unroll
        for (int mt = 0; mt < 2; mt++) {
            int arow = mrow0 + mt * 16 + (matA & 1) * 8 + rA;
            uint32_t off = (uint32_t)(arow * 128 + ks * 32 + (matA >> 1) * 16);
            ldm_x4(af[mt][0], af[mt][1], af[mt][2], af[mt][3], aBase + swz(off));
        }
        #pragma unroll
        for (int nt = 0; nt < 8; nt++) {
            uint32_t bf[2];
            int brow = nt * 8 + rA;
            uint32_t boff = (uint32_t)(brow * 128 + ks * 32 + matB * 16);
            ldm_x2(bf[0], bf[1], w1Base + swz(boff));
            mma16816(acc[0][nt], af[0], bf);
            mma16816(acc[1][nt], af[1], bf);
        }
    }

    // ---- epilogue 1: bias+relu, dot w2, deterministic lane reduce ----
    float p[4] = {0.f, 0.f, 0.f, 0.f};   // [mt*2 + rowhalf]
    #pragma unroll
    for (int mt = 0; mt < 2; mt++) {
        #pragma unroll
        for (int nt = 0; nt < 8; nt++) {
            int n = nt * 8 + (lane & 3) * 2;
            float w2a = sw2[n], w2b = sw2[n + 1];
            float b1a = sb1[n], b1b = sb1[n + 1];
            p[mt * 2 + 0] += fmaxf(acc[mt][nt][0] + b1a, 0.0f) * w2a
                           + fmaxf(acc[mt][nt][1] + b1b, 0.0f) * w2b;
            p[mt * 2 + 1] += fmaxf(acc[mt][nt][2] + b1a, 0.0f) * w2a
                           + fmaxf(acc[mt][nt][3] + b1b, 0.0f) * w2b;
        }
    }
    #pragma unroll
    for (int o = 1; o < 4; o <<= 1)
        #pragma unroll
        for (int i = 0; i < 4; i++)
            p[i] += __shfl_xor_sync(0xffffffffu, p[i], o);

    if ((lane & 3) == 0) {
        const float g  = sgate;
        const float bb = sbias2;
        float* dst = g_partial + (size_t)u * BATCH + m_base;
        int r = mrow0 + (lane >> 2);
        dst[r]          = g * (p[0] + bb);
        dst[r + 8]      = g * (p[1] + bb);
        dst[r + 16]     = g * (p[2] + bb);
        dst[r + 24]     = g * (p[3] + bb);
    }
}

// ---------------- deterministic final reduction ----------------
__global__ void reduce_kernel(float* __restrict__ out)
{
    const int b = blockIdx.x * blockDim.x + threadIdx.x;
    float s0 = 0.f, s1 = 0.f, s2 = 0.f, s3 = 0.f;
    #pragma unroll 4
    for (int u = 0; u < NU; u += 4) {
        s0 += g_partial[(size_t)(u + 0) * BATCH + b];
        s1 += g_partial[(size_t)(u + 1) * BATCH + b];
        s2 += g_partial[(size_t)(u + 2) * BATCH + b];
        s3 += g_partial[(size_t)(u + 3) * BATCH + b];
    }
    out[b] = (s0 + s1) + (s2 + s3);
}

extern "C" void kernel_launch(void* const* d_in, const int* in_sizes, int n_in,
                              void* d_out, int out_size)
{
    (void)in_sizes; (void)n_in; (void)out_size;

    const int*   mains      = (const int*)d_in[0];
    const int*   pairs      = (const int*)d_in[1];
    const int*   pairs_list = (const int*)d_in[2];
    const int*   offsets    = (const int*)d_in[3];
    const float* emb        = (const float*)d_in[4];
    const float* mw0 = (const float*)d_in[5];
    const float* mw1 = (const float*)d_in[6];
    const float* mw2 = (const float*)d_in[7];
    const float* mb0 = (const float*)d_in[8];
    const float* mb1 = (const float*)d_in[9];
    const float* mb2 = (const float*)d_in[10];
    const float* pw0 = (const float*)d_in[11];
    const float* pw1 = (const float*)d_in[12];
    const float* pw2 = (const float*)d_in[13];
    const float* pb0 = (const float*)d_in[14];
    const float* pb1 = (const float*)d_in[15];
    const float* pb2 = (const float*)d_in[16];
    const float* z_main  = (const float*)d_in[17];
    const float* z_pairs = (const float*)d_in[18];
    float* out = (float*)d_out;

    conv_weights<<<NU, 256>>>(mw0, mw1, pw0, pw1);
    conv_emb<<<64, 1024>>>(emb);
    conv_w2<<<(NU * 64 + 255) / 256, 256>>>(mw2, pw2);

    mlp_mma<<<dim3(NU, BATCH / MROWS), NTHREADS>>>(
        mains, pairs, pairs_list, offsets,
        mb0, mb1, mb2, pb0, pb1, pb2, z_main, z_pairs);

    reduce_kernel<<<BATCH / 256, 256>>>(out);
}